// round 12
// baseline (speedup 1.0000x reference)
#include <cuda_runtime.h>

#define Bn 128
#define Ln 1024
#define INF_ 136
#define F1 256
#define F2 512
#define Hn 256
#define G4 1024
#define WSP 260

// ---- scratch (device globals) ----
__device__ float g_W1T[INF_ * F1];
__device__ float g_W2T[F1 * F2];
__device__ float g_W4_0[(size_t)F2 * G4];   // packed [k][256][4]
__device__ float g_W4_1[(size_t)Hn * G4];
__device__ float g_W4_2[(size_t)Hn * G4];
__device__ float g_bsum0[G4];
__device__ float g_bsum1[G4];
__device__ float g_bsum2[G4];
__device__ float g_feat[(size_t)Ln * Bn * F2];   // [t][b][512]
__device__ float g_xg[(size_t)Ln * Bn * G4];     // [t*B+b][1024]
__device__ float g_hA[(size_t)Ln * Bn * Hn];
__device__ float g_hB[(size_t)Ln * Bn * Hn];
__device__ float g_hst[3][8][2][4096];           // [layer][rowgroup16][pingpong][unit*16+row]
__device__ unsigned g_grpctr[3][8 * 32];         // [layer][rg*32 + blk] (16 used + pad per rg)

// ---- f32x2 packed FMA ----
union F2U { float2 f; unsigned long long u; };
__device__ __forceinline__ float2 ffma2(float2 a, float2 b, float2 c) {
    F2U A, B, C, D;
    A.f = a; B.f = b; C.f = c;
    asm("fma.rn.f32x2 %0, %1, %2, %3;" : "=l"(D.u) : "l"(A.u), "l"(B.u), "l"(C.u));
    return D.f;
}

__device__ __forceinline__ float fast_sigmoid(float x) {
    return 1.f / (1.f + __expf(-x));
}
__device__ __forceinline__ float fast_tanh(float x) {
    return 2.f / (1.f + __expf(-2.f * x)) - 1.f;
}

// ---- fused prep ----
#define N1 (INF_ * F1)
#define N2 (F1 * F2)
#define N3 (F2 * G4)
#define N4 (Hn * G4)
#define NHST (3 * 8 * 4096)
__global__ void prep_kernel(const float* __restrict__ W1, const float* __restrict__ W2,
                            const float* __restrict__ w_ih0, const float* __restrict__ w_ih1,
                            const float* __restrict__ w_ih2,
                            const float* __restrict__ b_ih0, const float* __restrict__ b_hh0,
                            const float* __restrict__ b_ih1, const float* __restrict__ b_hh1,
                            const float* __restrict__ b_ih2, const float* __restrict__ b_hh2) {
    int i = blockIdx.x * blockDim.x + threadIdx.x;
    if (i < N1) {
        int r = i / INF_, c = i % INF_;
        g_W1T[c * F1 + r] = W1[i];
        return;
    }
    i -= N1;
    if (i < N2) {
        int r = i / F1, c = i % F1;
        g_W2T[c * F2 + r] = W2[i];
        return;
    }
    i -= N2;
    if (i < N3) {
        int k = i >> 10, rem = i & 1023, c = rem >> 2, g = rem & 3;
        g_W4_0[i] = w_ih0[(size_t)(g * 256 + c) * F2 + k];
        return;
    }
    i -= N3;
    if (i < N4) {
        int k = i >> 10, rem = i & 1023, c = rem >> 2, g = rem & 3;
        g_W4_1[i] = w_ih1[(size_t)(g * 256 + c) * Hn + k];
        return;
    }
    i -= N4;
    if (i < N4) {
        int k = i >> 10, rem = i & 1023, c = rem >> 2, g = rem & 3;
        g_W4_2[i] = w_ih2[(size_t)(g * 256 + c) * Hn + k];
        return;
    }
    i -= N4;
    if (i < G4) { g_bsum0[i] = b_ih0[i] + b_hh0[i]; return; }
    i -= G4;
    if (i < G4) { g_bsum1[i] = b_ih1[i] + b_hh1[i]; return; }
    i -= G4;
    if (i < G4) { g_bsum2[i] = b_ih2[i] + b_hh2[i]; return; }
    i -= G4;
    if (i < 3 * 256) { (&g_grpctr[0][0])[i] = 0u; return; }
    i -= 3 * 256;
    if (i < NHST) {
        int l = i >> 15;             // /(8*4096)
        int rem = i & 32767;
        int rg = rem >> 12;          // /4096
        int j = rem & 4095;
        g_hst[l][rg][0][j] = 0.f;
        return;
    }
}
#define PREP_TOTAL (N1 + N2 + N3 + 2 * N4 + 3 * G4 + 3 * 256 + NHST)

// ---- MLP v2 (unchanged, passing) ----
#define H1P 18
__global__ __launch_bounds__(256) void mlp2_kernel(const float* __restrict__ x,
                                                   const float* __restrict__ b1,
                                                   const float* __restrict__ b2) {
    __shared__ float xs[INF_ * 16];
    __shared__ float h1s[F1 * H1P];
    const int tid = threadIdx.x;
    const size_t row0 = (size_t)blockIdx.x * 16;

    const float* xr = x + row0 * INF_;
    for (int idx = tid; idx < 16 * INF_; idx += 256) {
        int r = idx / INF_, k = idx % INF_;
        xs[k * 16 + r] = xr[idx];
    }
    __syncthreads();

    {
        float2 acc[8];
        const float bb = b1[tid];
#pragma unroll
        for (int p = 0; p < 8; ++p) acc[p] = make_float2(bb, bb);
#pragma unroll 2
        for (int k = 0; k < INF_; ++k) {
            float w = g_W1T[k * F1 + tid];
            float2 w2 = make_float2(w, w);
            const float4* xp = (const float4*)(xs + k * 16);
#pragma unroll
            for (int q = 0; q < 4; ++q) {
                float4 v = xp[q];
                acc[2 * q]     = ffma2(make_float2(v.x, v.y), w2, acc[2 * q]);
                acc[2 * q + 1] = ffma2(make_float2(v.z, v.w), w2, acc[2 * q + 1]);
            }
        }
        float* hp = h1s + tid * H1P;
#pragma unroll
        for (int p = 0; p < 8; ++p) {
            *(float2*)(hp + 2 * p) = make_float2(fmaxf(acc[p].x, 0.f), fmaxf(acc[p].y, 0.f));
        }
    }
    __syncthreads();

    {
        float2 acc0[8], acc1[8];
        const float bb0 = b2[tid], bb1 = b2[tid + 256];
#pragma unroll
        for (int p = 0; p < 8; ++p) { acc0[p] = make_float2(bb0, bb0); acc1[p] = make_float2(bb1, bb1); }
#pragma unroll 2
        for (int k = 0; k < F1; ++k) {
            float w0 = g_W2T[k * F2 + tid];
            float w1 = g_W2T[k * F2 + tid + 256];
            float2 w20 = make_float2(w0, w0);
            float2 w21 = make_float2(w1, w1);
            const float* hp = h1s + k * H1P;
#pragma unroll
            for (int p = 0; p < 8; ++p) {
                float2 a = *(const float2*)(hp + 2 * p);
                acc0[p] = ffma2(a, w20, acc0[p]);
                acc1[p] = ffma2(a, w21, acc1[p]);
            }
        }
#pragma unroll
        for (int p = 0; p < 8; ++p) {
#pragma unroll
            for (int h = 0; h < 2; ++h) {
                size_t row = row0 + 2 * p + h;
                int b_ = (int)(row / Ln), t_ = (int)(row % Ln);
                float* fp = g_feat + ((size_t)t_ * Bn + b_) * F2;
                float v0 = h ? acc0[p].y : acc0[p].x;
                float v1 = h ? acc1[p].y : acc1[p].x;
                fp[tid] = fmaxf(v0, 0.f);
                fp[tid + 256] = fmaxf(v1, 0.f);
            }
        }
    }
}

// ---- xg GEMM (unchanged, passing) ----
template <int K, bool SRC_KMAJOR>
__global__ __launch_bounds__(256, 1) void xg2_kernel(const float* __restrict__ A,
                                                     const float* __restrict__ W4,
                                                     const float* __restrict__ bsum,
                                                     float* __restrict__ out) {
    extern __shared__ float As[];  // [K][36]
    const int tid = threadIdx.x;
    const int row0 = blockIdx.x * 32;

    if (SRC_KMAJOR) {
        const int t = row0 >> 7, b0 = row0 & 127;
        const float* base = A + ((size_t)t * K) * 128 + b0;
        for (int i = tid; i < K * 8; i += 256) {
            int k = i >> 3, r4 = (i & 7) * 4;
            *(float4*)(As + k * 36 + r4) = *(const float4*)(base + (size_t)k * 128 + r4);
        }
    } else {
        constexpr int KQ = K / 4;
        for (int i = tid; i < 32 * KQ; i += 256) {
            int r = i / KQ, kq = i % KQ;
            float4 v = *(const float4*)(A + (size_t)(row0 + r) * K + kq * 4);
            As[(kq * 4 + 0) * 36 + r] = v.x;
            As[(kq * 4 + 1) * 36 + r] = v.y;
            As[(kq * 4 + 2) * 36 + r] = v.z;
            As[(kq * 4 + 3) * 36 + r] = v.w;
        }
    }
    __syncthreads();

    float2 acc[16][4];
#pragma unroll
    for (int p = 0; p < 16; ++p)
#pragma unroll
        for (int g = 0; g < 4; ++g) acc[p][g] = make_float2(0.f, 0.f);

    const float4* wp = (const float4*)W4 + tid;
#pragma unroll 2
    for (int k = 0; k < K; ++k) {
        float4 w4 = wp[(size_t)k * 256];
        float2 w2[4];
        w2[0] = make_float2(w4.x, w4.x);
        w2[1] = make_float2(w4.y, w4.y);
        w2[2] = make_float2(w4.z, w4.z);
        w2[3] = make_float2(w4.w, w4.w);
        const float4* ap = (const float4*)(As + k * 36);
#pragma unroll
        for (int q = 0; q < 8; ++q) {
            float4 a4 = ap[q];
            float2 alo = make_float2(a4.x, a4.y);
            float2 ahi = make_float2(a4.z, a4.w);
#pragma unroll
            for (int g = 0; g < 4; ++g) {
                acc[2 * q][g]     = ffma2(alo, w2[g], acc[2 * q][g]);
                acc[2 * q + 1][g] = ffma2(ahi, w2[g], acc[2 * q + 1][g]);
            }
        }
    }

    float bb[4];
#pragma unroll
    for (int g = 0; g < 4; ++g) bb[g] = bsum[tid + g * 256];
#pragma unroll
    for (int p = 0; p < 16; ++p) {
        float* o0 = out + (size_t)(row0 + 2 * p) * G4 + tid;
        float* o1 = o0 + G4;
#pragma unroll
        for (int g = 0; g < 4; ++g) {
            o0[g * 256] = acc[p][g].x + bb[g];
            o1[g * 256] = acc[p][g].y + bb[g];
        }
    }
}

// ---- LSTM recurrence v8: 128 blocks (1/SM), 16u x 16r tiles, fan-in 16,
//      atomic-free per-block counters + parallel ballot poll ----
template <bool OUT_TBU>
__global__ __launch_bounds__(256) void lstm8_kernel(const float* __restrict__ xg,
                                                    const float* __restrict__ w_hh,
                                                    float* __restrict__ hout,
                                                    unsigned* __restrict__ ctrL,
                                                    float* __restrict__ hstL) {
    extern __shared__ float sm[];
    float* w_s = sm;                     // [64 cols][WSP]
    float* h_s = sm + 64 * WSP;          // [256 k][16 rows]
    float* gx  = sm + 64 * WSP + 4096;   // [64 cols][20]

    const int tid = threadIdx.x;
    const int bid = blockIdx.x;
    const int rg = bid >> 4;             // 0..7 rowgroup (16 rows)
    const int ug = bid & 15;             // 0..15 unit group (16 units)
    const int u0 = ug * 16;
    const int rbase = rg * 16;

    const int w = tid >> 5;
    const int lane = tid & 31;
    const int g = w & 3;                          // gate 0..3
    const int uh = w >> 2;                        // unit half 0..1
    const int uidx = uh * 8 + (lane & 7);         // 0..15 within-block unit
    const int c = g * 16 + uidx;                  // block-local col 0..63
    const int r0 = (lane >> 3) * 4;               // 0,4,8,12
    const int jcol = g * Hn + u0 + uidx;          // global gate col

    // stage w_hh: 64 cols x 256 k, k-contiguous, WSP conflict-free
    for (int i = tid; i < 64 * 256; i += 256) {
        int cc = i >> 8, k = i & 255;
        int jc = (cc >> 4) * Hn + u0 + (cc & 15);
        w_s[cc * WSP + k] = w_hh[(size_t)jc * Hn + k];
    }

    const int pu = tid >> 4;   // unit 0..15
    const int pr = tid & 15;   // row 0..15
    float cst = 0.f;
    unsigned* ctrRG = ctrL + rg * 32;      // 16 counters (+pad) for this rowgroup

    // first-step xg prefetch
    float x0, x1, x2, x3;
    {
        const float* xp = xg + ((size_t)rbase + r0) * G4 + jcol;
        x0 = xp[0]; x1 = xp[G4]; x2 = xp[2 * G4]; x3 = xp[3 * G4];
    }
    __syncthreads();

    for (int t = 0; t < Ln; ++t) {
        // stage h[t]: 16KB straight copy (global layout == smem layout [u][r] -> [k][16])
        {
            const float4* src = (const float4*)(hstL + (size_t)(rg * 2 + (t & 1)) * 4096);
            float4* dst = (float4*)h_s;
#pragma unroll
            for (int i = 0; i < 4; ++i) dst[tid + i * 256] = src[tid + i * 256];
        }
        __syncthreads();

        // gates: 1 col x 4 rows per lane, full k=256
        float2 a01 = make_float2(x0, x1);
        float2 a23 = make_float2(x2, x3);
        const float* wp = w_s + c * WSP;
        const float* hp = h_s + r0;
#pragma unroll 4
        for (int k = 0; k < Hn; k += 4) {
            float4 wv = *(const float4*)(wp + k);
            float4 h0 = *(const float4*)(hp + (k + 0) * 16);
            a01 = ffma2(make_float2(h0.x, h0.y), make_float2(wv.x, wv.x), a01);
            a23 = ffma2(make_float2(h0.z, h0.w), make_float2(wv.x, wv.x), a23);
            float4 h1 = *(const float4*)(hp + (k + 1) * 16);
            a01 = ffma2(make_float2(h1.x, h1.y), make_float2(wv.y, wv.y), a01);
            a23 = ffma2(make_float2(h1.z, h1.w), make_float2(wv.y, wv.y), a23);
            float4 h2 = *(const float4*)(hp + (k + 2) * 16);
            a01 = ffma2(make_float2(h2.x, h2.y), make_float2(wv.z, wv.z), a01);
            a23 = ffma2(make_float2(h2.z, h2.w), make_float2(wv.z, wv.z), a23);
            float4 h3 = *(const float4*)(hp + (k + 3) * 16);
            a01 = ffma2(make_float2(h3.x, h3.y), make_float2(wv.w, wv.w), a01);
            a23 = ffma2(make_float2(h3.z, h3.w), make_float2(wv.w, wv.w), a23);
        }
        *(float4*)(gx + c * 20 + r0) = make_float4(a01.x, a01.y, a23.x, a23.y);
        __syncthreads();

        // pointwise: all 256 threads, (unit pu, row pr)
        {
            float iv = gx[(0 * 16 + pu) * 20 + pr];
            float fv = gx[(1 * 16 + pu) * 20 + pr];
            float gv = gx[(2 * 16 + pu) * 20 + pr];
            float ov = gx[(3 * 16 + pu) * 20 + pr];
            iv = fast_sigmoid(iv);
            fv = fast_sigmoid(fv);
            gv = fast_tanh(gv);
            ov = fast_sigmoid(ov);
            cst = fv * cst + iv * gv;
            float hv = ov * fast_tanh(cst);
            hstL[(size_t)(rg * 2 + ((t + 1) & 1)) * 4096 + (u0 + pu) * 16 + pr] = hv;
            if (OUT_TBU)
                hout[((size_t)t * Bn + rbase + pr) * Hn + u0 + pu] = hv;
            else
                hout[((size_t)t * Hn + u0 + pu) * Bn + rbase + pr] = hv;
        }

        // prefetch next-step xg (independent of barrier)
        if (t + 1 < Ln) {
            const float* xp = xg + (((size_t)(t + 1)) * Bn + rbase + r0) * G4 + jcol;
            x0 = xp[0]; x1 = xp[G4]; x2 = xp[2 * G4]; x3 = xp[3 * G4];
        }

        __syncthreads();   // h stores complete block-wide
        // atomic-free barrier: own-counter release, parallel ballot poll
        if (tid == 0) {
            asm volatile("st.release.gpu.global.u32 [%0], %1;"
                         :: "l"(ctrRG + ug), "r"((unsigned)(t + 1)) : "memory");
        }
        if (w == 0) {
            const unsigned tgt = (unsigned)(t + 1);
            unsigned* cp = ctrRG + (lane & 15);
            while (true) {
                unsigned v;
                asm volatile("ld.acquire.gpu.global.u32 %0, [%1];" : "=r"(v) : "l"(cp) : "memory");
                if (__all_sync(0xffffffffu, v >= tgt)) break;
            }
        }
        __syncthreads();
    }
}

// ---- decision head (unchanged) ----
__global__ __launch_bounds__(256) void decision_kernel(const float* __restrict__ hseq,
                                                       const float* __restrict__ Wd,
                                                       const float* __restrict__ bd,
                                                       const int* __restrict__ length,
                                                       float* __restrict__ out) {
    const int b = blockIdx.x;
    const int tid = threadIdx.x;
    const int len = length[b];
    const float w = Wd[tid];
    float s0 = 0.f, s1 = 0.f, s2 = 0.f, s3 = 0.f;
    int t = 0;
    for (; t + 4 <= len; t += 4) {
        s0 = fmaf(hseq[((size_t)(t + 0) * Bn + b) * Hn + tid], w, s0);
        s1 = fmaf(hseq[((size_t)(t + 1) * Bn + b) * Hn + tid], w, s1);
        s2 = fmaf(hseq[((size_t)(t + 2) * Bn + b) * Hn + tid], w, s2);
        s3 = fmaf(hseq[((size_t)(t + 3) * Bn + b) * Hn + tid], w, s3);
    }
    for (; t < len; ++t) s0 = fmaf(hseq[((size_t)t * Bn + b) * Hn + tid], w, s0);
    float s = (s0 + s1) + (s2 + s3);
    __shared__ float red[256];
    red[tid] = s;
    __syncthreads();
    for (int st = 128; st > 0; st >>= 1) {
        if (tid < st) red[tid] += red[tid + st];
        __syncthreads();
    }
    if (tid == 0) out[b] = red[0] / (float)len + bd[0];
}

extern "C" void kernel_launch(void* const* d_in, const int* in_sizes, int n_in,
                              void* d_out, int out_size) {
    const float* x     = (const float*)d_in[0];
    const int* length  = (const int*)d_in[1];
    const float* W1    = (const float*)d_in[2];
    const float* b1    = (const float*)d_in[3];
    const float* W2    = (const float*)d_in[4];
    const float* b2    = (const float*)d_in[5];
    const float* w_ih0 = (const float*)d_in[6];
    const float* w_hh0 = (const float*)d_in[7];
    const float* b_ih0 = (const float*)d_in[8];
    const float* b_hh0 = (const float*)d_in[9];
    const float* w_ih1 = (const float*)d_in[10];
    const float* w_hh1 = (const float*)d_in[11];
    const float* b_ih1 = (const float*)d_in[12];
    const float* b_hh1 = (const float*)d_in[13];
    const float* w_ih2 = (const float*)d_in[14];
    const float* w_hh2 = (const float*)d_in[15];
    const float* b_ih2 = (const float*)d_in[16];
    const float* b_hh2 = (const float*)d_in[17];
    const float* Wd    = (const float*)d_in[18];
    const float* bd    = (const float*)d_in[19];
    float* out = (float*)d_out;

    float *dP0, *dP1, *dP2, *dB0, *dB1, *dB2, *dFeat, *dXg, *dHA, *dHB, *dHst;
    unsigned* dCtr;
    cudaGetSymbolAddress((void**)&dP0, g_W4_0);
    cudaGetSymbolAddress((void**)&dP1, g_W4_1);
    cudaGetSymbolAddress((void**)&dP2, g_W4_2);
    cudaGetSymbolAddress((void**)&dB0, g_bsum0);
    cudaGetSymbolAddress((void**)&dB1, g_bsum1);
    cudaGetSymbolAddress((void**)&dB2, g_bsum2);
    cudaGetSymbolAddress((void**)&dFeat, g_feat);
    cudaGetSymbolAddress((void**)&dXg, g_xg);
    cudaGetSymbolAddress((void**)&dHA, g_hA);
    cudaGetSymbolAddress((void**)&dHB, g_hB);
    cudaGetSymbolAddress((void**)&dHst, g_hst);
    cudaGetSymbolAddress((void**)&dCtr, g_grpctr);

    const int xg_smem512 = 512 * 36 * sizeof(float);
    const int xg_smem256 = 256 * 36 * sizeof(float);
    const int lstm_smem = (64 * WSP + 4096 + 64 * 20) * sizeof(float);
    cudaFuncSetAttribute(xg2_kernel<F2, false>, cudaFuncAttributeMaxDynamicSharedMemorySize, xg_smem512);
    cudaFuncSetAttribute(xg2_kernel<Hn, true>, cudaFuncAttributeMaxDynamicSharedMemorySize, xg_smem256);
    cudaFuncSetAttribute(lstm8_kernel<false>, cudaFuncAttributeMaxDynamicSharedMemorySize, lstm_smem);
    cudaFuncSetAttribute(lstm8_kernel<true>, cudaFuncAttributeMaxDynamicSharedMemorySize, lstm_smem);

    prep_kernel<<<(PREP_TOTAL + 255) / 256, 256>>>(W1, W2, w_ih0, w_ih1, w_ih2,
                                                   b_ih0, b_hh0, b_ih1, b_hh1, b_ih2, b_hh2);

    const int nrows = Bn * Ln;
    mlp2_kernel<<<nrows / 16, 256>>>(x, b1, b2);

    // layer 0 (lstm is the 4th launch -> profiled by ncu)
    xg2_kernel<F2, false><<<nrows / 32, 256, xg_smem512>>>(dFeat, dP0, dB0, dXg);
    lstm8_kernel<false><<<128, 256, lstm_smem>>>(dXg, w_hh0, dHA, dCtr + 0 * 256, dHst + 0 * (8 * 2 * 4096));
    // layer 1
    xg2_kernel<Hn, true><<<nrows / 32, 256, xg_smem256>>>(dHA, dP1, dB1, dXg);
    lstm8_kernel<false><<<128, 256, lstm_smem>>>(dXg, w_hh1, dHB, dCtr + 1 * 256, dHst + 1 * (8 * 2 * 4096));
    // layer 2
    xg2_kernel<Hn, true><<<nrows / 32, 256, xg_smem256>>>(dHB, dP2, dB2, dXg);
    lstm8_kernel<true><<<128, 256, lstm_smem>>>(dXg, w_hh2, dHA, dCtr + 2 * 256, dHst + 2 * (8 * 2 * 4096));

    decision_kernel<<<Bn, 256>>>(dHA, Wd, bd, length, out);
}

// round 13
// speedup vs baseline: 1.3257x; 1.3257x over previous
#include <cuda_runtime.h>

#define Bn 128
#define Ln 1024
#define INF_ 136
#define F1 256
#define F2 512
#define Hn 256
#define G4 1024

// ---- scratch (device globals) ----
__device__ float g_W1T[INF_ * F1];
__device__ float g_W2T[F1 * F2];
__device__ float g_W4_0[(size_t)F2 * G4];        // packed [k][256][4] for layer0 xg
__device__ float g_bsum0[G4];
__device__ float g_bsum1[G4];
__device__ float g_bsum2[G4];
__device__ float g_feat[(size_t)Ln * Bn * F2];   // [t][b][512]
__device__ float g_xg[(size_t)Ln * Bn * G4];     // layer0 xg [t*B+b][1024]
__device__ float g_hA[(size_t)Ln * Bn * Hn];     // layer2 h sequence [t][b][u]
__device__ float g_hst3[3 * 2 * Hn * Bn];        // [layer][pp][u*128+b]
__device__ unsigned g_ctr2[64];                  // [rg][32-pad]

// ---- f32x2 packed FMA ----
union F2U { float2 f; unsigned long long u; };
__device__ __forceinline__ float2 ffma2(float2 a, float2 b, float2 c) {
    F2U A, B, C, D;
    A.f = a; B.f = b; C.f = c;
    asm("fma.rn.f32x2 %0, %1, %2, %3;" : "=l"(D.u) : "l"(A.u), "l"(B.u), "l"(C.u));
    return D.f;
}

__device__ __forceinline__ float fast_sigmoid(float x) {
    return 1.f / (1.f + __expf(-x));
}
__device__ __forceinline__ float fast_tanh(float x) {
    return 2.f / (1.f + __expf(-2.f * x)) - 1.f;
}

// ---- fused prep ----
#define N1 (INF_ * F1)
#define N2 (F1 * F2)
#define N3 (F2 * G4)
#define NHST3 (3 * 2 * Hn * Bn)
__global__ void prep_kernel(const float* __restrict__ W1, const float* __restrict__ W2,
                            const float* __restrict__ w_ih0,
                            const float* __restrict__ b_ih0, const float* __restrict__ b_hh0,
                            const float* __restrict__ b_ih1, const float* __restrict__ b_hh1,
                            const float* __restrict__ b_ih2, const float* __restrict__ b_hh2) {
    int i = blockIdx.x * blockDim.x + threadIdx.x;
    if (i < N1) {
        int r = i / INF_, c = i % INF_;
        g_W1T[c * F1 + r] = W1[i];
        return;
    }
    i -= N1;
    if (i < N2) {
        int r = i / F1, c = i % F1;
        g_W2T[c * F2 + r] = W2[i];
        return;
    }
    i -= N2;
    if (i < N3) {
        int k = i >> 10, rem = i & 1023, c = rem >> 2, g = rem & 3;
        g_W4_0[i] = w_ih0[(size_t)(g * 256 + c) * F2 + k];
        return;
    }
    i -= N3;
    if (i < G4) { g_bsum0[i] = b_ih0[i] + b_hh0[i]; return; }
    i -= G4;
    if (i < G4) { g_bsum1[i] = b_ih1[i] + b_hh1[i]; return; }
    i -= G4;
    if (i < G4) { g_bsum2[i] = b_ih2[i] + b_hh2[i]; return; }
    i -= G4;
    if (i < 64) { g_ctr2[i] = 0u; return; }
    i -= 64;
    if (i < NHST3) { g_hst3[i] = 0.f; return; }
}
#define PREP_TOTAL (N1 + N2 + N3 + 3 * G4 + 64 + NHST3)

// ---- MLP v2 (unchanged, passing) ----
#define H1P 18
__global__ __launch_bounds__(256) void mlp2_kernel(const float* __restrict__ x,
                                                   const float* __restrict__ b1,
                                                   const float* __restrict__ b2) {
    __shared__ float xs[INF_ * 16];
    __shared__ float h1s[F1 * H1P];
    const int tid = threadIdx.x;
    const size_t row0 = (size_t)blockIdx.x * 16;

    const float* xr = x + row0 * INF_;
    for (int idx = tid; idx < 16 * INF_; idx += 256) {
        int r = idx / INF_, k = idx % INF_;
        xs[k * 16 + r] = xr[idx];
    }
    __syncthreads();

    {
        float2 acc[8];
        const float bb = b1[tid];
#pragma unroll
        for (int p = 0; p < 8; ++p) acc[p] = make_float2(bb, bb);
#pragma unroll 2
        for (int k = 0; k < INF_; ++k) {
            float w = g_W1T[k * F1 + tid];
            float2 w2 = make_float2(w, w);
            const float4* xp = (const float4*)(xs + k * 16);
#pragma unroll
            for (int q = 0; q < 4; ++q) {
                float4 v = xp[q];
                acc[2 * q]     = ffma2(make_float2(v.x, v.y), w2, acc[2 * q]);
                acc[2 * q + 1] = ffma2(make_float2(v.z, v.w), w2, acc[2 * q + 1]);
            }
        }
        float* hp = h1s + tid * H1P;
#pragma unroll
        for (int p = 0; p < 8; ++p) {
            *(float2*)(hp + 2 * p) = make_float2(fmaxf(acc[p].x, 0.f), fmaxf(acc[p].y, 0.f));
        }
    }
    __syncthreads();

    {
        float2 acc0[8], acc1[8];
        const float bb0 = b2[tid], bb1 = b2[tid + 256];
#pragma unroll
        for (int p = 0; p < 8; ++p) { acc0[p] = make_float2(bb0, bb0); acc1[p] = make_float2(bb1, bb1); }
#pragma unroll 2
        for (int k = 0; k < F1; ++k) {
            float w0 = g_W2T[k * F2 + tid];
            float w1 = g_W2T[k * F2 + tid + 256];
            float2 w20 = make_float2(w0, w0);
            float2 w21 = make_float2(w1, w1);
            const float* hp = h1s + k * H1P;
#pragma unroll
            for (int p = 0; p < 8; ++p) {
                float2 a = *(const float2*)(hp + 2 * p);
                acc0[p] = ffma2(a, w20, acc0[p]);
                acc1[p] = ffma2(a, w21, acc1[p]);
            }
        }
#pragma unroll
        for (int p = 0; p < 8; ++p) {
#pragma unroll
            for (int h = 0; h < 2; ++h) {
                size_t row = row0 + 2 * p + h;
                int b_ = (int)(row / Ln), t_ = (int)(row % Ln);
                float* fp = g_feat + ((size_t)t_ * Bn + b_) * F2;
                float v0 = h ? acc0[p].y : acc0[p].x;
                float v1 = h ? acc1[p].y : acc1[p].x;
                fp[tid] = fmaxf(v0, 0.f);
                fp[tid + 256] = fmaxf(v1, 0.f);
            }
        }
    }
}

// ---- xg GEMM for layer0 (unchanged, passing) ----
template <int K, bool SRC_KMAJOR>
__global__ __launch_bounds__(256, 1) void xg2_kernel(const float* __restrict__ A,
                                                     const float* __restrict__ W4,
                                                     const float* __restrict__ bsum,
                                                     float* __restrict__ out) {
    extern __shared__ float As[];  // [K][36]
    const int tid = threadIdx.x;
    const int row0 = blockIdx.x * 32;

    {
        constexpr int KQ = K / 4;
        for (int i = tid; i < 32 * KQ; i += 256) {
            int r = i / KQ, kq = i % KQ;
            float4 v = *(const float4*)(A + (size_t)(row0 + r) * K + kq * 4);
            As[(kq * 4 + 0) * 36 + r] = v.x;
            As[(kq * 4 + 1) * 36 + r] = v.y;
            As[(kq * 4 + 2) * 36 + r] = v.z;
            As[(kq * 4 + 3) * 36 + r] = v.w;
        }
    }
    __syncthreads();

    float2 acc[16][4];
#pragma unroll
    for (int p = 0; p < 16; ++p)
#pragma unroll
        for (int g = 0; g < 4; ++g) acc[p][g] = make_float2(0.f, 0.f);

    const float4* wp = (const float4*)W4 + tid;
#pragma unroll 2
    for (int k = 0; k < K; ++k) {
        float4 w4 = wp[(size_t)k * 256];
        float2 w2[4];
        w2[0] = make_float2(w4.x, w4.x);
        w2[1] = make_float2(w4.y, w4.y);
        w2[2] = make_float2(w4.z, w4.z);
        w2[3] = make_float2(w4.w, w4.w);
        const float4* ap = (const float4*)(As + k * 36);
#pragma unroll
        for (int q = 0; q < 8; ++q) {
            float4 a4 = ap[q];
            float2 alo = make_float2(a4.x, a4.y);
            float2 ahi = make_float2(a4.z, a4.w);
#pragma unroll
            for (int g = 0; g < 4; ++g) {
                acc[2 * q][g]     = ffma2(alo, w2[g], acc[2 * q][g]);
                acc[2 * q + 1][g] = ffma2(ahi, w2[g], acc[2 * q + 1][g]);
            }
        }
    }

    float bb[4];
#pragma unroll
    for (int g = 0; g < 4; ++g) bb[g] = bsum[tid + g * 256];
#pragma unroll
    for (int p = 0; p < 16; ++p) {
        float* o0 = out + (size_t)(row0 + 2 * p) * G4 + tid;
        float* o1 = o0 + G4;
#pragma unroll
        for (int g = 0; g < 4; ++g) {
            o0[g * 256] = acc[p][g].x + bb[g];
            o1[g * 256] = acc[p][g].y + bb[g];
        }
    }
}

// ---- pipelined 3-layer LSTM: 128 persistent blocks, 1026 ticks ----
// block = (rg in 0..1: rows rg*64..+63) x (ug in 0..63: units ug*4..+3)
// warp (rh,kq): rows rh*32+..., k-quarter kq. lane (rq,cp): 4 rows x 4 cols.
__device__ __forceinline__ void gemm16(const float* __restrict__ hb,
                                       const float* __restrict__ wb,
                                       float2 acc[4][2], int kiter) {
#pragma unroll 4
    for (int k = 0; k < kiter; ++k) {
        float4 wv = *(const float4*)(wb + k * 16);
        float4 hv = *(const float4*)(hb + k * 64);
        float2 wlo = make_float2(wv.x, wv.y);
        float2 whi = make_float2(wv.z, wv.w);
        acc[0][0] = ffma2(make_float2(hv.x, hv.x), wlo, acc[0][0]);
        acc[0][1] = ffma2(make_float2(hv.x, hv.x), whi, acc[0][1]);
        acc[1][0] = ffma2(make_float2(hv.y, hv.y), wlo, acc[1][0]);
        acc[1][1] = ffma2(make_float2(hv.y, hv.y), whi, acc[1][1]);
        acc[2][0] = ffma2(make_float2(hv.z, hv.z), wlo, acc[2][0]);
        acc[2][1] = ffma2(make_float2(hv.z, hv.z), whi, acc[2][1]);
        acc[3][0] = ffma2(make_float2(hv.w, hv.w), wlo, acc[3][0]);
        acc[3][1] = ffma2(make_float2(hv.w, hv.w), whi, acc[3][1]);
    }
}

__global__ __launch_bounds__(256) void lstm_pipe_kernel(
    const float* __restrict__ xg,
    const float* __restrict__ w_hh0,
    const float* __restrict__ w_hh1, const float* __restrict__ w_ih1,
    const float* __restrict__ w_hh2, const float* __restrict__ w_ih2,
    const float* __restrict__ bs1, const float* __restrict__ bs2,
    float* __restrict__ hout, unsigned* __restrict__ ctr,
    float* __restrict__ hst) {
    extern __shared__ float sm[];
    float* W0s = sm;                  // [256][16]
    float* W1s = W0s + 256 * 16;      // [512][16]
    float* W2s = W1s + 512 * 16;      // [512][16]
    float* HA  = W2s + 512 * 16;      // [256][64]
    float* HB  = HA + 256 * 64;       // [256][64]
    float* gex = HB;                  // alias after L2 gemm: [12][64][16]

    const int tid = threadIdx.x;
    const int bid = blockIdx.x;
    const int rg = bid >> 6, ug = bid & 63;
    const int u0 = ug * 4, rbase = rg * 64;

    const int w = tid >> 5, lane = tid & 31;
    const int kq = w & 3, rh = w >> 2;
    const int rq = lane >> 2, cp = lane & 3;
    const int rloc = rh * 32 + rq * 4;
    const int c0 = cp * 4;

    // stage weights once: [k][16 cols], col c -> gate c>>2, unit u0+(c&3)
    for (int i = tid; i < 256 * 16; i += 256) {
        int k = i >> 4, c = i & 15;
        int jc = (c >> 2) * Hn + u0 + (c & 3);
        W0s[i] = w_hh0[(size_t)jc * Hn + k];
    }
    for (int i = tid; i < 512 * 16; i += 256) {
        int k = i >> 4, c = i & 15;
        int jc = (c >> 2) * Hn + u0 + (c & 3);
        W1s[i] = (k < 256) ? w_hh1[(size_t)jc * Hn + k] : w_ih1[(size_t)jc * Hn + (k - 256)];
        W2s[i] = (k < 256) ? w_hh2[(size_t)jc * Hn + k] : w_ih2[(size_t)jc * Hn + (k - 256)];
    }

    const int pu = tid >> 6, pr = tid & 63;   // pointwise: unit u0+pu, row rbase+pr
    float b1v[4], b2v[4];
#pragma unroll
    for (int g = 0; g < 4; ++g) {
        b1v[g] = bs1[g * Hn + u0 + pu];
        b2v[g] = bs2[g * Hn + u0 + pu];
    }
    float cst0 = 0.f, cst1 = 0.f, cst2 = 0.f;
    unsigned* myctr = ctr + rg * 32;

    for (int tau = 0; tau < Ln + 2; ++tau) {
        const int s0 = tau, s1 = tau - 1, s2 = tau - 2;
        const bool a0 = (s0 < Ln);
        const bool a1 = (s1 >= 0) && (s1 < Ln);
        const bool a2 = (s2 >= 0);

        // prefetch layer0 xg (kq==0 warps): rows rloc.., cols cp*256+u0..+3
        float4 xv0, xv1, xv2, xv3;
        if (a0 && kq == 0) {
            const float* xp = xg + ((size_t)(s0 * Bn + rbase + rloc)) * G4 + cp * 256 + u0;
            xv0 = *(const float4*)(xp);
            xv1 = *(const float4*)(xp + G4);
            xv2 = *(const float4*)(xp + 2 * G4);
            xv3 = *(const float4*)(xp + 3 * G4);
        }

        // stage HA <- h0(tau-1), HB <- h1(tau-2)
        {
            const float* sa = hst + (size_t)(0 * 2 + ((tau - 1) & 1)) * 32768;
            const float* sb = hst + (size_t)(1 * 2 + (tau & 1)) * 32768;   // (tau-2)&1 == tau&1
            for (int i = tid; i < 4096; i += 256) {
                int u = i >> 4, r4 = (i & 15) << 2;
                *(float4*)(HA + u * 64 + r4) = *(const float4*)(sa + u * 128 + rbase + r4);
                *(float4*)(HB + u * 64 + r4) = *(const float4*)(sb + u * 128 + rbase + r4);
            }
        }
        __syncthreads();

        // L0: gates0 = xg0[s0] + h0(s0-1) @ w_hh0  (K=256, 4-way k-split)
        float2 A0[4][2];
#pragma unroll
        for (int r = 0; r < 4; ++r) { A0[r][0] = make_float2(0.f, 0.f); A0[r][1] = make_float2(0.f, 0.f); }
        if (a0) {
            gemm16(HA + kq * 64 * 64 + rloc, W0s + kq * 64 * 16 + c0, A0, 64);
            if (kq == 0) {
                A0[0][0].x += xv0.x; A0[0][0].y += xv0.y; A0[0][1].x += xv0.z; A0[0][1].y += xv0.w;
                A0[1][0].x += xv1.x; A0[1][0].y += xv1.y; A0[1][1].x += xv1.z; A0[1][1].y += xv1.w;
                A0[2][0].x += xv2.x; A0[2][0].y += xv2.y; A0[2][1].x += xv2.z; A0[2][1].y += xv2.w;
                A0[3][0].x += xv3.x; A0[3][0].y += xv3.y; A0[3][1].x += xv3.z; A0[3][1].y += xv3.w;
            }
        }

        // L1: gates1 = h1(s1-1)@w_hh1 + h0(s1)@w_ih1 (K=512: kq0,1->HB/Whh; kq2,3->HA/Wih)
        float2 A1[4][2];
#pragma unroll
        for (int r = 0; r < 4; ++r) { A1[r][0] = make_float2(0.f, 0.f); A1[r][1] = make_float2(0.f, 0.f); }
        if (a1) {
            const float* hb = (kq < 2) ? (HB + kq * 128 * 64 + rloc) : (HA + (kq - 2) * 128 * 64 + rloc);
            gemm16(hb, W1s + kq * 128 * 16 + c0, A1, 128);
        }
        __syncthreads();   // all HA reads (L0, L1) complete

        // restage HA <- h2(tau-3)
        {
            const float* sc = hst + (size_t)(2 * 2 + ((tau - 1) & 1)) * 32768;  // (tau-3)&1 == (tau-1)&1
            for (int i = tid; i < 4096; i += 256) {
                int u = i >> 4, r4 = (i & 15) << 2;
                *(float4*)(HA + u * 64 + r4) = *(const float4*)(sc + u * 128 + rbase + r4);
            }
        }
        __syncthreads();

        // L2: gates2 = h2(s2-1)@w_hh2 + h1(s2)@w_ih2 (kq0,1->HA/Whh; kq2,3->HB/Wih)
        float2 A2[4][2];
#pragma unroll
        for (int r = 0; r < 4; ++r) { A2[r][0] = make_float2(0.f, 0.f); A2[r][1] = make_float2(0.f, 0.f); }
        if (a2) {
            const float* hb = (kq < 2) ? (HA + kq * 128 * 64 + rloc) : (HB + (kq - 2) * 128 * 64 + rloc);
            gemm16(hb, W2s + kq * 128 * 16 + c0, A2, 128);
        }
        __syncthreads();   // HB reads complete -> gex (aliases HB) writable

        // write gate partials [lsel*4+kq][row][16c]
#pragma unroll
        for (int r = 0; r < 4; ++r) {
            float* g0 = gex + ((0 * 4 + kq) * 64 + rloc + r) * 16 + c0;
            float* g1 = gex + ((1 * 4 + kq) * 64 + rloc + r) * 16 + c0;
            float* g2 = gex + ((2 * 4 + kq) * 64 + rloc + r) * 16 + c0;
            *(float2*)(g0) = A0[r][0]; *(float2*)(g0 + 2) = A0[r][1];
            *(float2*)(g1) = A1[r][0]; *(float2*)(g1 + 2) = A1[r][1];
            *(float2*)(g2) = A2[r][0]; *(float2*)(g2 + 2) = A2[r][1];
        }
        __syncthreads();

        // pointwise per active layer; thread owns (unit u0+pu, row rbase+pr)
#pragma unroll
        for (int l = 0; l < 3; ++l) {
            bool act = (l == 0) ? a0 : (l == 1) ? a1 : a2;
            if (!act) continue;
            float gv[4];
#pragma unroll
            for (int g = 0; g < 4; ++g) {
                const float* gp = gex + (l * 4 * 64 + pr) * 16 + g * 4 + pu;
                gv[g] = gp[0] + gp[1024] + gp[2048] + gp[3072];
            }
            float* cstp = (l == 0) ? &cst0 : (l == 1) ? &cst1 : &cst2;
            if (l == 1) { gv[0] += b1v[0]; gv[1] += b1v[1]; gv[2] += b1v[2]; gv[3] += b1v[3]; }
            if (l == 2) { gv[0] += b2v[0]; gv[1] += b2v[1]; gv[2] += b2v[2]; gv[3] += b2v[3]; }
            float iv = fast_sigmoid(gv[0]);
            float fv = fast_sigmoid(gv[1]);
            float gg = fast_tanh(gv[2]);
            float ov = fast_sigmoid(gv[3]);
            float cs = fv * (*cstp) + iv * gg;
            *cstp = cs;
            float hv = ov * fast_tanh(cs);
            int s = (l == 0) ? s0 : (l == 1) ? s1 : s2;
            hst[(size_t)(l * 2 + (s & 1)) * 32768 + (u0 + pu) * 128 + rbase + pr] = hv;
            if (l == 2)
                hout[((size_t)s * Bn + rbase + pr) * Hn + u0 + pu] = hv;
        }
        __syncthreads();

        // per-rowgroup barrier (fan-in 64)
        if (tid == 0) {
            asm volatile("red.release.gpu.global.add.u32 [%0], %1;" :: "l"(myctr), "r"(1u) : "memory");
        }
        if (tid == 32) {
            const unsigned target = (unsigned)(tau + 1) * 64u;
            unsigned v;
            do {
                asm volatile("ld.acquire.gpu.global.u32 %0, [%1];" : "=r"(v) : "l"(myctr) : "memory");
            } while (v < target);
        }
        __syncthreads();
    }
}

// ---- decision head (unchanged) ----
__global__ __launch_bounds__(256) void decision_kernel(const float* __restrict__ hseq,
                                                       const float* __restrict__ Wd,
                                                       const float* __restrict__ bd,
                                                       const int* __restrict__ length,
                                                       float* __restrict__ out) {
    const int b = blockIdx.x;
    const int tid = threadIdx.x;
    const int len = length[b];
    const float w = Wd[tid];
    float s0 = 0.f, s1 = 0.f, s2 = 0.f, s3 = 0.f;
    int t = 0;
    for (; t + 4 <= len; t += 4) {
        s0 = fmaf(hseq[((size_t)(t + 0) * Bn + b) * Hn + tid], w, s0);
        s1 = fmaf(hseq[((size_t)(t + 1) * Bn + b) * Hn + tid], w, s1);
        s2 = fmaf(hseq[((size_t)(t + 2) * Bn + b) * Hn + tid], w, s2);
        s3 = fmaf(hseq[((size_t)(t + 3) * Bn + b) * Hn + tid], w, s3);
    }
    for (; t < len; ++t) s0 = fmaf(hseq[((size_t)t * Bn + b) * Hn + tid], w, s0);
    float s = (s0 + s1) + (s2 + s3);
    __shared__ float red[256];
    red[tid] = s;
    __syncthreads();
    for (int st = 128; st > 0; st >>= 1) {
        if (tid < st) red[tid] += red[tid + st];
        __syncthreads();
    }
    if (tid == 0) out[b] = red[0] / (float)len + bd[0];
}

extern "C" void kernel_launch(void* const* d_in, const int* in_sizes, int n_in,
                              void* d_out, int out_size) {
    const float* x     = (const float*)d_in[0];
    const int* length  = (const int*)d_in[1];
    const float* W1    = (const float*)d_in[2];
    const float* b1    = (const float*)d_in[3];
    const float* W2    = (const float*)d_in[4];
    const float* b2    = (const float*)d_in[5];
    const float* w_ih0 = (const float*)d_in[6];
    const float* w_hh0 = (const float*)d_in[7];
    const float* b_ih0 = (const float*)d_in[8];
    const float* b_hh0 = (const float*)d_in[9];
    const float* w_ih1 = (const float*)d_in[10];
    const float* w_hh1 = (const float*)d_in[11];
    const float* b_ih1 = (const float*)d_in[12];
    const float* b_hh1 = (const float*)d_in[13];
    const float* w_ih2 = (const float*)d_in[14];
    const float* w_hh2 = (const float*)d_in[15];
    const float* b_ih2 = (const float*)d_in[16];
    const float* b_hh2 = (const float*)d_in[17];
    const float* Wd    = (const float*)d_in[18];
    const float* bd    = (const float*)d_in[19];
    float* out = (float*)d_out;

    float *dP0, *dB0, *dB1, *dB2, *dFeat, *dXg, *dHA, *dHst;
    unsigned* dCtr;
    cudaGetSymbolAddress((void**)&dP0, g_W4_0);
    cudaGetSymbolAddress((void**)&dB0, g_bsum0);
    cudaGetSymbolAddress((void**)&dB1, g_bsum1);
    cudaGetSymbolAddress((void**)&dB2, g_bsum2);
    cudaGetSymbolAddress((void**)&dFeat, g_feat);
    cudaGetSymbolAddress((void**)&dXg, g_xg);
    cudaGetSymbolAddress((void**)&dHA, g_hA);
    cudaGetSymbolAddress((void**)&dHst, g_hst3);
    cudaGetSymbolAddress((void**)&dCtr, g_ctr2);

    const int xg_smem512 = 512 * 36 * sizeof(float);
    const int pipe_smem = (16 * (256 + 512 + 512) + 2 * 256 * 64) * sizeof(float);  // 208 KB
    cudaFuncSetAttribute(xg2_kernel<F2, false>, cudaFuncAttributeMaxDynamicSharedMemorySize, xg_smem512);
    cudaFuncSetAttribute(lstm_pipe_kernel, cudaFuncAttributeMaxDynamicSharedMemorySize, pipe_smem);

    prep_kernel<<<(PREP_TOTAL + 255) / 256, 256>>>(W1, W2, w_ih0,
                                                   b_ih0, b_hh0, b_ih1, b_hh1, b_ih2, b_hh2);

    const int nrows = Bn * Ln;
    mlp2_kernel<<<nrows / 16, 256>>>(x, b1, b2);

    // layer-0 gate input projection (precomputed)
    xg2_kernel<F2, false><<<nrows / 32, 256, xg_smem512>>>(dFeat, dP0, dB0, dXg);

    // pipelined 3-layer recurrence (4th launch -> profiled by ncu)
    lstm_pipe_kernel<<<128, 256, pipe_smem>>>(dXg, w_hh0, w_hh1, w_ih1, w_hh2, w_ih2,
                                              dB1, dB2, dHA, dCtr, dHst);

    decision_kernel<<<Bn, 256>>>(dHA, Wd, bd, length, out);
}